// round 15
// baseline (speedup 1.0000x reference)
#include <cuda_runtime.h>
#include <cuda_fp16.h>
#include <cuda_bf16.h>
#include <cstdint>

#define N_NODES 100000
#define N_EDGES 20000
#define N_INC   800000
#define TD      384
#define HID     128
#define NBE     79
#define NBN     391
#define NBI     3125

// ---------------- device scratch ----------------
__device__ __align__(16) __half g_h16A[N_NODES * HID];
__device__ __align__(16) __half g_h16B[N_NODES * HID];
__device__ __align__(16) __half g_ef16[N_EDGES * HID];
__device__ __align__(16) __half g_Wt16[HID * TD];   // W transposed [n][k] fp16
__device__ int   g_ecnt[N_EDGES];
__device__ int   g_ncnt[N_NODES];
__device__ int   g_ecur[N_EDGES];
__device__ int   g_ncur[N_NODES];
__device__ int   g_eoff[N_EDGES + 1];
__device__ int   g_noff[N_NODES + 1];
__device__ int   g_enodes[N_INC];
__device__ int   g_nedges[N_INC];
__device__ int   g_bsumE[128];
__device__ int   g_bsumN[512];
__device__ float g_gsum[HID];    // column sums of h (fused in gemm epilogue)
__device__ float g_gsum2[HID];   // column sums of h after layer 1
__device__ __align__(16) float g_scale[HID];

// ---------------- CSR construction ----------------
__global__ void zero_counts() {
    int i = blockIdx.x * blockDim.x + threadIdx.x;
    if (i < N_EDGES) { g_ecnt[i] = 0; g_ecur[i] = 0; }
    if (i < N_NODES) { g_ncnt[i] = 0; g_ncur[i] = 0; }
}

__global__ void hist_kernel(const int* __restrict__ ni, const int* __restrict__ ei) {
    int i = blockIdx.x * blockDim.x + threadIdx.x;
    if (i < N_INC) {
        atomicAdd(&g_ecnt[ei[i]], 1);
        atomicAdd(&g_ncnt[ni[i]], 1);
    }
}

__global__ void segB() {
    int b = blockIdx.x;
    const int* __restrict__ cnt;
    int n;
    int* bs;
    if (b < NBE) { cnt = g_ecnt; n = N_EDGES; bs = g_bsumE; }
    else { b -= NBE; cnt = g_ncnt; n = N_NODES; bs = g_bsumN; }
    __shared__ int s[256];
    int t = threadIdx.x;
    int i = b * 256 + t;
    s[t] = (i < n) ? cnt[i] : 0;
    __syncthreads();
    for (int o = 128; o > 0; o >>= 1) {
        if (t < o) s[t] += s[t + o];
        __syncthreads();
    }
    if (t == 0) bs[b] = s[0];
}

__global__ void scanB() {
    int* bs = blockIdx.x ? g_bsumN : g_bsumE;
    int nb = blockIdx.x ? NBN : NBE;
    __shared__ int s[512];
    int t = threadIdx.x;
    int v = (t < nb) ? bs[t] : 0;
    s[t] = v;
    __syncthreads();
    for (int o = 1; o < 512; o <<= 1) {
        int x = (t >= o) ? s[t - o] : 0;
        __syncthreads();
        s[t] += x;
        __syncthreads();
    }
    if (t < nb) bs[t] = s[t] - v;
}

__global__ void scanfB() {
    int b = blockIdx.x;
    const int* __restrict__ cnt;
    const int* bs;
    int* off;
    int n;
    if (b < NBE) { cnt = g_ecnt; bs = g_bsumE; off = g_eoff; n = N_EDGES; }
    else { b -= NBE; cnt = g_ncnt; bs = g_bsumN; off = g_noff; n = N_NODES; }
    __shared__ int s[256];
    int t = threadIdx.x;
    int i = b * 256 + t;
    int v = (i < n) ? cnt[i] : 0;
    s[t] = v;
    __syncthreads();
    for (int o = 1; o < 256; o <<= 1) {
        int x = (t >= o) ? s[t - o] : 0;
        __syncthreads();
        s[t] += x;
        __syncthreads();
    }
    if (i < n) off[i] = bs[b] + s[t] - v;
    if (i == 0) off[n] = N_INC;
}

__global__ void csr_fill(const int* __restrict__ ni, const int* __restrict__ ei) {
    int i = blockIdx.x * blockDim.x + threadIdx.x;
    if (i >= N_INC) return;
    int e = ei[i], n = ni[i];
    int pe = g_eoff[e] + atomicAdd(&g_ecur[e], 1);
    g_enodes[pe] = n;
    int pn = g_noff[n] + atomicAdd(&g_ncur[n], 1);
    g_nedges[pn] = e;
}

// ---------------- W prep: fp32 [k][n] -> fp16 transposed [n][k]; zero gsums ----
__global__ void w_prep(const float* __restrict__ W) {
    int i = blockIdx.x * blockDim.x + threadIdx.x;
    if (i < HID) { g_gsum[i] = 0.f; g_gsum2[i] = 0.f; }
    if (i >= TD * HID) return;
    int n = i & (HID - 1);
    int k = i >> 7;
    g_Wt16[n * TD + k] = __float2half_rn(W[k * HID + n]);
}

// ---------------- fp16 tensor-core GEMM + fused column sums -------------------
// 128 threads / 64-row block tile -> 4 CTAs/SM (4 independent sync domains).
// Per-warp tiling identical to before (32x64, 6 K-tiles of 64).
#define SSTR 72
#define KT   64
#define BM   64

#define LDSM4(r, addr) \
    asm volatile("ldmatrix.sync.aligned.m8n8.x4.shared.b16 {%0,%1,%2,%3}, [%4];" \
        : "=r"((r)[0]), "=r"((r)[1]), "=r"((r)[2]), "=r"((r)[3]) : "r"(addr))

#define MMA16816H(c, a, b0, b1) \
    asm volatile("mma.sync.aligned.m16n8k16.row.col.f32.f16.f16.f32 " \
        "{%0,%1,%2,%3},{%4,%5,%6,%7},{%8,%9},{%0,%1,%2,%3};" \
        : "+f"((c)[0]), "+f"((c)[1]), "+f"((c)[2]), "+f"((c)[3]) \
        : "r"((a)[0]), "r"((a)[1]), "r"((a)[2]), "r"((a)[3]), "r"(b0), "r"(b1))

__global__ void __launch_bounds__(128, 4) gemm_mma(
    const float* __restrict__ A, const float* __restrict__ bias) {
    extern __shared__ char dynsmem[];
    __half* sA = (__half*)dynsmem;             // [64][72]
    __half* sW = sA + BM * SSTR;               // [n][k] [128][72]
    __shared__ float sWsum[4][64];             // per-warp column-sum slabs

    const int tid = threadIdx.x;
    const int lane = tid & 31;
    const int wid = tid >> 5;                  // 0..3
    const int wr = wid >> 1;                   // 0..1 (m)
    const int wc = wid & 1;                    // 0..1 (n)
    const int bm = blockIdx.x * BM;

    const unsigned sb = (unsigned)__cvta_generic_to_shared(dynsmem);
    const unsigned Ab = sb;
    const unsigned Wb = sb + BM * SSTR * 2;

    const int aRow = ((lane >> 3) & 1) * 8 + (lane & 7);
    const int aColH = (lane >> 4) * 8;
    const unsigned aOff0 = (unsigned)(((wr * 32 + 0  + aRow) * SSTR + aColH) * 2);
    const unsigned aOff1 = (unsigned)(((wr * 32 + 16 + aRow) * SSTR + aColH) * 2);
    const int bRow = (lane >> 4) * 8 + (lane & 7);
    const int bColH = ((lane >> 3) & 1) * 8;
    const unsigned bOff = (unsigned)(((wc * 64 + bRow) * SSTR + bColH) * 2);

    // A loading: 128 threads cover 64 rows x 64 k (half-row each)
    const int lm = tid >> 1;                   // 0..63
    const int lk = (tid & 1) * 32;
    int arow = bm + lm;
    if (arow >= N_NODES) arow = N_NODES - 1;
    const float* Ap = A + (size_t)arow * TD + lk;
    // W loading: each thread loads one full 64-half row of the k-tile
    const __half* Wp = g_Wt16 + tid * TD;

    float c[2][8][4];
#pragma unroll
    for (int i = 0; i < 2; i++)
#pragma unroll
        for (int j = 0; j < 8; j++)
#pragma unroll
            for (int q = 0; q < 4; q++) c[i][j][q] = 0.f;

    for (int t = 0; t < TD / KT; t++) {
        const int k0 = t * KT;
#pragma unroll
        for (int cc = 0; cc < 8; cc++) {
            float4 v = *(const float4*)(Ap + k0 + cc * 4);
            __half2 p0 = __floats2half2_rn(v.x, v.y);
            __half2 p1 = __floats2half2_rn(v.z, v.w);
            int so = lm * SSTR + lk + cc * 4;
            *(__half2*)(sA + so)     = p0;
            *(__half2*)(sA + so + 2) = p1;
        }
#pragma unroll
        for (int cc = 0; cc < 8; cc++) {
            uint4 vw = *(const uint4*)(Wp + k0 + cc * 8);
            *(uint4*)(sW + tid * SSTR + cc * 8) = vw;
        }
        __syncthreads();

#pragma unroll
        for (int kk = 0; kk < KT / 16; kk++) {
            const unsigned ko = kk * 32;
            unsigned a[2][4];
            LDSM4(a[0], Ab + aOff0 + ko);
            LDSM4(a[1], Ab + aOff1 + ko);
#pragma unroll
            for (int jj = 0; jj < 4; jj++) {
                unsigned b[4];
                LDSM4(b, Wb + bOff + jj * (16 * SSTR * 2) + ko);
#pragma unroll
                for (int i = 0; i < 2; i++) {
                    MMA16816H(c[i][2 * jj],     a[i], b[0], b[1]);
                    MMA16816H(c[i][2 * jj + 1], a[i], b[2], b[3]);
                }
            }
        }
        __syncthreads();
    }

    // epilogue: store + register-accumulated column partials
    float rs[16];
#pragma unroll
    for (int q = 0; q < 16; q++) rs[q] = 0.f;

#pragma unroll
    for (int i = 0; i < 2; i++) {
        int r0 = bm + wr * 32 + i * 16 + (lane >> 2);
        int r1 = r0 + 8;
        bool ok0 = r0 < N_NODES, ok1 = r1 < N_NODES;
#pragma unroll
        for (int j = 0; j < 8; j++) {
            int n = wc * 64 + j * 8 + (lane & 3) * 2;
            float2 bb = *(const float2*)(bias + n);
            float v00 = c[i][j][0] + bb.x, v01 = c[i][j][1] + bb.y;
            float v10 = c[i][j][2] + bb.x, v11 = c[i][j][3] + bb.y;
            if (ok0) *(__half2*)(g_h16A + (size_t)r0 * HID + n) =
                __floats2half2_rn(v00, v01);
            if (ok1) *(__half2*)(g_h16A + (size_t)r1 * HID + n) =
                __floats2half2_rn(v10, v11);
            rs[2 * j]     += (ok0 ? v00 : 0.f) + (ok1 ? v10 : 0.f);
            rs[2 * j + 1] += (ok0 ? v01 : 0.f) + (ok1 ? v11 : 0.f);
        }
    }
#pragma unroll
    for (int q = 0; q < 16; q++) {
        rs[q] += __shfl_xor_sync(0xffffffffu, rs[q], 4);
        rs[q] += __shfl_xor_sync(0xffffffffu, rs[q], 8);
        rs[q] += __shfl_xor_sync(0xffffffffu, rs[q], 16);
    }
    if (lane < 4) {
#pragma unroll
        for (int j = 0; j < 8; j++) {
            sWsum[wid][j * 8 + lane * 2]     = rs[2 * j];
            sWsum[wid][j * 8 + lane * 2 + 1] = rs[2 * j + 1];
        }
    }
    __syncthreads();
    if (tid < HID) {
        int wcq = tid >> 6, idx = tid & 63;   // cols 0-63 <- wids 0,2; 64-127 <- 1,3
        float s = sWsum[wcq][idx] + sWsum[wcq + 2][idx];
        atomicAdd(&g_gsum[tid], s);
    }
}

// ---------------- hypernetwork scale (reads fused column sums) ----------------
__global__ void mk_scale(int sel,
                         const float* __restrict__ W1, const float* __restrict__ b1,
                         const float* __restrict__ W2, const float* __restrict__ b2) {
    __shared__ float g[HID];
    __shared__ float t1[HID];
    int j = threadIdx.x;
    g[j] = (sel ? g_gsum2[j] : g_gsum[j]) * (1.0f / (float)N_NODES);
    __syncthreads();
    float a = b1[j];
#pragma unroll 8
    for (int k = 0; k < HID; k++) a += g[k] * W1[k * HID + j];
    t1[j] = fmaxf(a, 0.f);
    __syncthreads();
    float o = b2[j];
#pragma unroll 8
    for (int k = 0; k < HID; k++) o += t1[k] * W2[k * HID + j];
    g_scale[j] = o;
}

// ---------------- aggregation ----------------
__device__ __forceinline__ void acc8(float* a, uint4 v) {
    __half2 h0 = *reinterpret_cast<__half2*>(&v.x);
    __half2 h1 = *reinterpret_cast<__half2*>(&v.y);
    __half2 h2 = *reinterpret_cast<__half2*>(&v.z);
    __half2 h3 = *reinterpret_cast<__half2*>(&v.w);
    float2 f0 = __half22float2(h0), f1 = __half22float2(h1);
    float2 f2 = __half22float2(h2), f3 = __half22float2(h3);
    a[0] += f0.x; a[1] += f0.y; a[2] += f1.x; a[3] += f1.y;
    a[4] += f2.x; a[5] += f2.y; a[6] += f3.x; a[7] += f3.y;
}

__device__ __forceinline__ void seg_sum(const int* __restrict__ ids, int beg, int m,
                                        const __half* __restrict__ h,
                                        int lane, float* acc) {
    const int half = lane >> 4;
    const int cpos = lane & 15;
    for (int c = 0; c < m; c += 32) {
        int rem = m - c;
        if (rem > 32) rem = 32;
        int myid = (lane < rem) ? ids[beg + c + lane] : 0;
        int t = 0;
        for (; t + 8 <= rem; t += 8) {
#pragma unroll
            for (int p = 0; p < 4; p++) {
                int id = __shfl_sync(0xffffffffu, myid, t + 2 * p + half);
                uint4 v = *(const uint4*)(h + (size_t)id * HID + cpos * 8);
                acc8(acc, v);
            }
        }
        for (; t < rem; t += 2) {
            int idx = t + half;
            bool valid = idx < rem;
            int id = __shfl_sync(0xffffffffu, myid, valid ? idx : t);
            uint4 v = *(const uint4*)(h + (size_t)id * HID + cpos * 8);
            if (valid) acc8(acc, v);
        }
    }
#pragma unroll
    for (int i = 0; i < 8; i++)
        acc[i] += __shfl_xor_sync(0xffffffffu, acc[i], 16);
}

__global__ void edge_agg(int sel) {
    const __half* __restrict__ h = sel ? g_h16B : g_h16A;
    int w = (blockIdx.x * blockDim.x + threadIdx.x) >> 5;
    int lane = threadIdx.x & 31;
    if (w >= N_EDGES) return;
    int beg = g_eoff[w], end = g_eoff[w + 1];
    int m = end - beg;
    float acc[8] = {0.f, 0.f, 0.f, 0.f, 0.f, 0.f, 0.f, 0.f};
    seg_sum(g_enodes, beg, m, h, lane, acc);
    if (lane < 16) {
        float inv = 1.0f / fmaxf((float)m, 1.0f);
        __half2 p0 = __floats2half2_rn(acc[0] * inv, acc[1] * inv);
        __half2 p1 = __floats2half2_rn(acc[2] * inv, acc[3] * inv);
        __half2 p2 = __floats2half2_rn(acc[4] * inv, acc[5] * inv);
        __half2 p3 = __floats2half2_rn(acc[6] * inv, acc[7] * inv);
        uint4 u;
        u.x = *reinterpret_cast<unsigned*>(&p0);
        u.y = *reinterpret_cast<unsigned*>(&p1);
        u.z = *reinterpret_cast<unsigned*>(&p2);
        u.w = *reinterpret_cast<unsigned*>(&p3);
        ((uint4*)(g_ef16 + (size_t)w * HID))[lane] = u;
    }
}

// to_out: 0 = write g_h16B (fp16) + accumulate column sums into g_gsum2;
//         1 = write d_out (fp32)
__global__ void node_agg(float* __restrict__ out_arg, int to_out) {
    __shared__ float sCol[HID];
    int w = (blockIdx.x * blockDim.x + threadIdx.x) >> 5;
    int lane = threadIdx.x & 31;
    int tid = threadIdx.x;
    if (!to_out) {
        if (tid < HID) sCol[tid] = 0.f;
        __syncthreads();
    }
    int beg = g_noff[w], end = g_noff[w + 1];
    int m = end - beg;
    float acc[8] = {0.f, 0.f, 0.f, 0.f, 0.f, 0.f, 0.f, 0.f};
    seg_sum(g_nedges, beg, m, g_ef16, lane, acc);
    float inv = 1.0f / fmaxf((float)m, 1.0f);
    float r[8];
    if (lane < 16) {
        float4 s0 = ((const float4*)g_scale)[lane * 2];
        float4 s1 = ((const float4*)g_scale)[lane * 2 + 1];
        r[0] = fmaxf(acc[0] * inv * s0.x, 0.f);
        r[1] = fmaxf(acc[1] * inv * s0.y, 0.f);
        r[2] = fmaxf(acc[2] * inv * s0.z, 0.f);
        r[3] = fmaxf(acc[3] * inv * s0.w, 0.f);
        r[4] = fmaxf(acc[4] * inv * s1.x, 0.f);
        r[5] = fmaxf(acc[5] * inv * s1.y, 0.f);
        r[6] = fmaxf(acc[6] * inv * s1.z, 0.f);
        r[7] = fmaxf(acc[7] * inv * s1.w, 0.f);
        if (to_out) {
            float* orow = out_arg + (size_t)w * HID + lane * 8;
            *(float4*)orow = make_float4(r[0], r[1], r[2], r[3]);
            *(float4*)(orow + 4) = make_float4(r[4], r[5], r[6], r[7]);
        } else {
            __half2 p0 = __floats2half2_rn(r[0], r[1]);
            __half2 p1 = __floats2half2_rn(r[2], r[3]);
            __half2 p2 = __floats2half2_rn(r[4], r[5]);
            __half2 p3 = __floats2half2_rn(r[6], r[7]);
            uint4 u;
            u.x = *reinterpret_cast<unsigned*>(&p0);
            u.y = *reinterpret_cast<unsigned*>(&p1);
            u.z = *reinterpret_cast<unsigned*>(&p2);
            u.w = *reinterpret_cast<unsigned*>(&p3);
            ((uint4*)(g_h16B + (size_t)w * HID))[lane] = u;
#pragma unroll
            for (int i = 0; i < 8; i++)
                atomicAdd(&sCol[lane * 8 + i], r[i]);
        }
    }
    if (!to_out) {
        __syncthreads();
        if (tid < HID) atomicAdd(&g_gsum2[tid], sCol[tid]);
    }
}

// ---------------- launch (R11 schedule, verbatim) ----------------
extern "C" void kernel_launch(void* const* d_in, const int* in_sizes, int n_in,
                              void* d_out, int out_size) {
    const float* text = (const float*)d_in[0];
    const float* Wp   = (const float*)d_in[1];
    const float* bp   = (const float*)d_in[2];
    const float* W1a  = (const float*)d_in[3];
    const float* b1a  = (const float*)d_in[4];
    const float* W2a  = (const float*)d_in[5];
    const float* b2a  = (const float*)d_in[6];
    const float* W1b  = (const float*)d_in[7];
    const float* b1b  = (const float*)d_in[8];
    const float* W2b  = (const float*)d_in[9];
    const float* b2b  = (const float*)d_in[10];
    const int* node_idx = (const int*)d_in[11];
    const int* edge_idx = (const int*)d_in[12];

    const int SMEM_GEMM = (BM + HID) * SSTR * 2;  // 27648 B

    static cudaStream_t s2 = nullptr;
    static cudaEvent_t ev0, evCSR, evG, evS1, evN0, evS2;
    if (!s2) {
        cudaStreamCreateWithFlags(&s2, cudaStreamNonBlocking);
        cudaEventCreateWithFlags(&ev0,   cudaEventDisableTiming);
        cudaEventCreateWithFlags(&evCSR, cudaEventDisableTiming);
        cudaEventCreateWithFlags(&evG,   cudaEventDisableTiming);
        cudaEventCreateWithFlags(&evS1,  cudaEventDisableTiming);
        cudaEventCreateWithFlags(&evN0,  cudaEventDisableTiming);
        cudaEventCreateWithFlags(&evS2,  cudaEventDisableTiming);
        cudaFuncSetAttribute(gemm_mma,
            cudaFuncAttributeMaxDynamicSharedMemorySize, SMEM_GEMM);
    }

    cudaEventRecord(ev0, 0);
    cudaStreamWaitEvent(s2, ev0, 0);

    // launches: #1,#2 on s2; #3 w_prep; #4 gemm_mma (ncu profiles the 4th)
    zero_counts<<<NBN, 256, 0, s2>>>();
    hist_kernel<<<NBI, 256, 0, s2>>>(node_idx, edge_idx);
    w_prep<<<(TD * HID + 255) / 256, 256>>>(Wp);
    gemm_mma<<<(N_NODES + BM - 1) / BM, 128, SMEM_GEMM>>>(text, bp);
    cudaEventRecord(evG, 0);

    segB<<<NBE + NBN, 256, 0, s2>>>();
    scanB<<<2, 512, 0, s2>>>();
    scanfB<<<NBE + NBN, 256, 0, s2>>>();
    csr_fill<<<NBI, 256, 0, s2>>>(node_idx, edge_idx);
    cudaEventRecord(evCSR, s2);

    // layer-1 hypernet on s2 (needs g_gsum from gemm), overlaps edge_agg
    cudaStreamWaitEvent(s2, evG, 0);
    mk_scale<<<1, 128, 0, s2>>>(0, W1a, b1a, W2a, b2a);
    cudaEventRecord(evS1, s2);

    cudaStreamWaitEvent((cudaStream_t)0, evCSR, 0);
    edge_agg<<<N_EDGES / 8, 256>>>(0);
    cudaStreamWaitEvent((cudaStream_t)0, evS1, 0);
    node_agg<<<N_NODES / 8, 256>>>((float*)d_out, 0);
    cudaEventRecord(evN0, 0);

    // layer-2 hypernet on s2 (needs g_gsum2 from node_agg), overlaps edge_agg
    cudaStreamWaitEvent(s2, evN0, 0);
    mk_scale<<<1, 128, 0, s2>>>(1, W1b, b1b, W2b, b2b);
    cudaEventRecord(evS2, s2);

    edge_agg<<<N_EDGES / 8, 256>>>(1);
    cudaStreamWaitEvent((cudaStream_t)0, evS2, 0);
    node_agg<<<N_NODES / 8, 256>>>((float*)d_out, 1);
}

// round 16
// speedup vs baseline: 1.0894x; 1.0894x over previous
#include <cuda_runtime.h>
#include <cuda_fp16.h>
#include <cuda_bf16.h>
#include <cstdint>

#define N_NODES 100000
#define N_EDGES 20000
#define N_INC   800000
#define TD      384
#define HID     128
#define NBE     79
#define NBN     391
#define NBI     3125

// ---------------- device scratch ----------------
__device__ __align__(16) __half g_h16A[N_NODES * HID];
__device__ __align__(16) __half g_h16B[N_NODES * HID];
__device__ __align__(16) __half g_ef16[N_EDGES * HID];
__device__ __align__(16) __half g_Wt16[HID * TD];   // W transposed [n][k] fp16
__device__ int   g_ecnt[N_EDGES];
__device__ int   g_ncnt[N_NODES];
__device__ int   g_ecur[N_EDGES];
__device__ int   g_ncur[N_NODES];
__device__ int   g_eoff[N_EDGES + 1];
__device__ int   g_noff[N_NODES + 1];
__device__ int   g_enodes[N_INC];
__device__ int   g_nedges[N_INC];
__device__ int   g_bsumE[128];
__device__ int   g_bsumN[512];
__device__ float g_gsum[HID];    // column sums of h (fused in gemm epilogue)
__device__ float g_gsum2[HID];   // column sums of h after layer 1
__device__ __align__(16) float g_scale[HID];

// ---------------- CSR construction ----------------
__global__ void zero_counts() {
    int i = blockIdx.x * blockDim.x + threadIdx.x;
    if (i < N_EDGES) { g_ecnt[i] = 0; g_ecur[i] = 0; }
    if (i < N_NODES) { g_ncnt[i] = 0; g_ncur[i] = 0; }
}

__global__ void hist_kernel(const int* __restrict__ ni, const int* __restrict__ ei) {
    int i = blockIdx.x * blockDim.x + threadIdx.x;
    if (i < N_INC) {
        atomicAdd(&g_ecnt[ei[i]], 1);
        atomicAdd(&g_ncnt[ni[i]], 1);
    }
}

__global__ void segB() {
    int b = blockIdx.x;
    const int* __restrict__ cnt;
    int n;
    int* bs;
    if (b < NBE) { cnt = g_ecnt; n = N_EDGES; bs = g_bsumE; }
    else { b -= NBE; cnt = g_ncnt; n = N_NODES; bs = g_bsumN; }
    __shared__ int s[256];
    int t = threadIdx.x;
    int i = b * 256 + t;
    s[t] = (i < n) ? cnt[i] : 0;
    __syncthreads();
    for (int o = 128; o > 0; o >>= 1) {
        if (t < o) s[t] += s[t + o];
        __syncthreads();
    }
    if (t == 0) bs[b] = s[0];
}

__global__ void scanB() {
    int* bs = blockIdx.x ? g_bsumN : g_bsumE;
    int nb = blockIdx.x ? NBN : NBE;
    __shared__ int s[512];
    int t = threadIdx.x;
    int v = (t < nb) ? bs[t] : 0;
    s[t] = v;
    __syncthreads();
    for (int o = 1; o < 512; o <<= 1) {
        int x = (t >= o) ? s[t - o] : 0;
        __syncthreads();
        s[t] += x;
        __syncthreads();
    }
    if (t < nb) bs[t] = s[t] - v;
}

__global__ void scanfB() {
    int b = blockIdx.x;
    const int* __restrict__ cnt;
    const int* bs;
    int* off;
    int n;
    if (b < NBE) { cnt = g_ecnt; bs = g_bsumE; off = g_eoff; n = N_EDGES; }
    else { b -= NBE; cnt = g_ncnt; bs = g_bsumN; off = g_noff; n = N_NODES; }
    __shared__ int s[256];
    int t = threadIdx.x;
    int i = b * 256 + t;
    int v = (i < n) ? cnt[i] : 0;
    s[t] = v;
    __syncthreads();
    for (int o = 1; o < 256; o <<= 1) {
        int x = (t >= o) ? s[t - o] : 0;
        __syncthreads();
        s[t] += x;
        __syncthreads();
    }
    if (i < n) off[i] = bs[b] + s[t] - v;
    if (i == 0) off[n] = N_INC;
}

__global__ void csr_fill(const int* __restrict__ ni, const int* __restrict__ ei) {
    int i = blockIdx.x * blockDim.x + threadIdx.x;
    if (i >= N_INC) return;
    int e = ei[i], n = ni[i];
    int pe = g_eoff[e] + atomicAdd(&g_ecur[e], 1);
    g_enodes[pe] = n;
    int pn = g_noff[n] + atomicAdd(&g_ncur[n], 1);
    g_nedges[pn] = e;
}

// ---------------- W prep: fp32 [k][n] -> fp16 transposed [n][k]; zero gsums ----
__global__ void w_prep(const float* __restrict__ W) {
    int i = blockIdx.x * blockDim.x + threadIdx.x;
    if (i < HID) { g_gsum[i] = 0.f; g_gsum2[i] = 0.f; }
    if (i >= TD * HID) return;
    int n = i & (HID - 1);
    int k = i >> 7;
    g_Wt16[n * TD + k] = __float2half_rn(W[k * HID + n]);
}

// ---------------- fp16 tensor-core GEMM + fused column sums (R14 form) --------
#define SSTR 72
#define KT   64

#define LDSM4(r, addr) \
    asm volatile("ldmatrix.sync.aligned.m8n8.x4.shared.b16 {%0,%1,%2,%3}, [%4];" \
        : "=r"((r)[0]), "=r"((r)[1]), "=r"((r)[2]), "=r"((r)[3]) : "r"(addr))

#define MMA16816H(c, a, b0, b1) \
    asm volatile("mma.sync.aligned.m16n8k16.row.col.f32.f16.f16.f32 " \
        "{%0,%1,%2,%3},{%4,%5,%6,%7},{%8,%9},{%0,%1,%2,%3};" \
        : "+f"((c)[0]), "+f"((c)[1]), "+f"((c)[2]), "+f"((c)[3]) \
        : "r"((a)[0]), "r"((a)[1]), "r"((a)[2]), "r"((a)[3]), "r"(b0), "r"(b1))

__global__ void __launch_bounds__(256, 2) gemm_mma(
    const float* __restrict__ A, const float* __restrict__ bias) {
    extern __shared__ char dynsmem[];
    __half* sA = (__half*)dynsmem;             // [128][72]
    __half* sW = sA + 128 * SSTR;              // [n][k] [128][72]
    __shared__ float sWsum[8][64];             // per-warp column-sum slabs

    const int tid = threadIdx.x;
    const int lane = tid & 31;
    const int wid = tid >> 5;
    const int wr = wid >> 1;
    const int wc = wid & 1;
    const int bm = blockIdx.x * 128;

    const unsigned sb = (unsigned)__cvta_generic_to_shared(dynsmem);
    const unsigned Ab = sb;
    const unsigned Wb = sb + 128 * SSTR * 2;

    const int aRow = ((lane >> 3) & 1) * 8 + (lane & 7);
    const int aColH = (lane >> 4) * 8;
    const unsigned aOff0 = (unsigned)(((wr * 32 + 0  + aRow) * SSTR + aColH) * 2);
    const unsigned aOff1 = (unsigned)(((wr * 32 + 16 + aRow) * SSTR + aColH) * 2);
    const int bRow = (lane >> 4) * 8 + (lane & 7);
    const int bColH = ((lane >> 3) & 1) * 8;
    const unsigned bOff = (unsigned)(((wc * 64 + bRow) * SSTR + bColH) * 2);

    const int lm = tid >> 1;
    const int lk = (tid & 1) * 32;
    int arow = bm + lm;
    if (arow >= N_NODES) arow = N_NODES - 1;
    const float* Ap = A + (size_t)arow * TD + lk;
    const __half* Wp = g_Wt16 + lm * TD + lk;

    float c[2][8][4];
#pragma unroll
    for (int i = 0; i < 2; i++)
#pragma unroll
        for (int j = 0; j < 8; j++)
#pragma unroll
            for (int q = 0; q < 4; q++) c[i][j][q] = 0.f;

    for (int t = 0; t < TD / KT; t++) {
        const int k0 = t * KT;
#pragma unroll
        for (int cc = 0; cc < 8; cc++) {
            float4 v = *(const float4*)(Ap + k0 + cc * 4);
            __half2 p0 = __floats2half2_rn(v.x, v.y);
            __half2 p1 = __floats2half2_rn(v.z, v.w);
            int so = lm * SSTR + lk + cc * 4;
            *(__half2*)(sA + so)     = p0;
            *(__half2*)(sA + so + 2) = p1;
        }
#pragma unroll
        for (int cc = 0; cc < 4; cc++) {
            uint4 vw = *(const uint4*)(Wp + k0 + cc * 8);
            *(uint4*)(sW + lm * SSTR + lk + cc * 8) = vw;
        }
        __syncthreads();

#pragma unroll
        for (int kk = 0; kk < KT / 16; kk++) {
            const unsigned ko = kk * 32;
            unsigned a[2][4];
            LDSM4(a[0], Ab + aOff0 + ko);
            LDSM4(a[1], Ab + aOff1 + ko);
#pragma unroll
            for (int jj = 0; jj < 4; jj++) {
                unsigned b[4];
                LDSM4(b, Wb + bOff + jj * (16 * SSTR * 2) + ko);
#pragma unroll
                for (int i = 0; i < 2; i++) {
                    MMA16816H(c[i][2 * jj],     a[i], b[0], b[1]);
                    MMA16816H(c[i][2 * jj + 1], a[i], b[2], b[3]);
                }
            }
        }
        __syncthreads();
    }

    // epilogue: store + register-accumulated column partials
    float rs[16];
#pragma unroll
    for (int q = 0; q < 16; q++) rs[q] = 0.f;

#pragma unroll
    for (int i = 0; i < 2; i++) {
        int r0 = bm + wr * 32 + i * 16 + (lane >> 2);
        int r1 = r0 + 8;
        bool ok0 = r0 < N_NODES, ok1 = r1 < N_NODES;
#pragma unroll
        for (int j = 0; j < 8; j++) {
            int n = wc * 64 + j * 8 + (lane & 3) * 2;
            float2 bb = *(const float2*)(bias + n);
            float v00 = c[i][j][0] + bb.x, v01 = c[i][j][1] + bb.y;
            float v10 = c[i][j][2] + bb.x, v11 = c[i][j][3] + bb.y;
            if (ok0) *(__half2*)(g_h16A + (size_t)r0 * HID + n) =
                __floats2half2_rn(v00, v01);
            if (ok1) *(__half2*)(g_h16A + (size_t)r1 * HID + n) =
                __floats2half2_rn(v10, v11);
            rs[2 * j]     += (ok0 ? v00 : 0.f) + (ok1 ? v10 : 0.f);
            rs[2 * j + 1] += (ok0 ? v01 : 0.f) + (ok1 ? v11 : 0.f);
        }
    }
#pragma unroll
    for (int q = 0; q < 16; q++) {
        rs[q] += __shfl_xor_sync(0xffffffffu, rs[q], 4);
        rs[q] += __shfl_xor_sync(0xffffffffu, rs[q], 8);
        rs[q] += __shfl_xor_sync(0xffffffffu, rs[q], 16);
    }
    if (lane < 4) {
#pragma unroll
        for (int j = 0; j < 8; j++) {
            sWsum[wid][j * 8 + lane * 2]     = rs[2 * j];
            sWsum[wid][j * 8 + lane * 2 + 1] = rs[2 * j + 1];
        }
    }
    __syncthreads();
    if (tid < HID) {
        int wcq = tid >> 6, idx = tid & 63;
        float s = sWsum[wcq][idx] + sWsum[wcq + 2][idx]
                + sWsum[wcq + 4][idx] + sWsum[wcq + 6][idx];
        atomicAdd(&g_gsum[tid], s);
    }
}

// ---------------- hypernetwork scale (reads fused column sums) ----------------
__global__ void mk_scale(int sel,
                         const float* __restrict__ W1, const float* __restrict__ b1,
                         const float* __restrict__ W2, const float* __restrict__ b2) {
    __shared__ float g[HID];
    __shared__ float t1[HID];
    int j = threadIdx.x;
    g[j] = (sel ? g_gsum2[j] : g_gsum[j]) * (1.0f / (float)N_NODES);
    __syncthreads();
    float a = b1[j];
#pragma unroll 8
    for (int k = 0; k < HID; k++) a += g[k] * W1[k * HID + j];
    t1[j] = fmaxf(a, 0.f);
    __syncthreads();
    float o = b2[j];
#pragma unroll 8
    for (int k = 0; k < HID; k++) o += t1[k] * W2[k * HID + j];
    g_scale[j] = o;
}

// ---------------- aggregation (with index prefetch across chunks) -------------
__device__ __forceinline__ void acc8(float* a, uint4 v) {
    __half2 h0 = *reinterpret_cast<__half2*>(&v.x);
    __half2 h1 = *reinterpret_cast<__half2*>(&v.y);
    __half2 h2 = *reinterpret_cast<__half2*>(&v.z);
    __half2 h3 = *reinterpret_cast<__half2*>(&v.w);
    float2 f0 = __half22float2(h0), f1 = __half22float2(h1);
    float2 f2 = __half22float2(h2), f3 = __half22float2(h3);
    a[0] += f0.x; a[1] += f0.y; a[2] += f1.x; a[3] += f1.y;
    a[4] += f2.x; a[5] += f2.y; a[6] += f3.x; a[7] += f3.y;
}

__device__ __forceinline__ void seg_sum(const int* __restrict__ ids, int beg, int m,
                                        const __half* __restrict__ h,
                                        int lane, float* acc) {
    const int half = lane >> 4;
    const int cpos = lane & 15;
    // prefetch chunk 0's indices
    int myid = (lane < m) ? ids[beg + lane] : 0;
    for (int c = 0; c < m; c += 32) {
        int rem = m - c;
        if (rem > 32) rem = 32;
        // prefetch next chunk's indices before the gather loop (latency overlap)
        int nc = c + 32;
        int nextid = (nc < m && lane < m - nc) ? ids[beg + nc + lane] : 0;
        int t = 0;
        for (; t + 8 <= rem; t += 8) {
#pragma unroll
            for (int p = 0; p < 4; p++) {
                int id = __shfl_sync(0xffffffffu, myid, t + 2 * p + half);
                uint4 v = *(const uint4*)(h + (size_t)id * HID + cpos * 8);
                acc8(acc, v);
            }
        }
        for (; t < rem; t += 2) {
            int idx = t + half;
            bool valid = idx < rem;
            int id = __shfl_sync(0xffffffffu, myid, valid ? idx : t);
            uint4 v = *(const uint4*)(h + (size_t)id * HID + cpos * 8);
            if (valid) acc8(acc, v);
        }
        myid = nextid;
    }
#pragma unroll
    for (int i = 0; i < 8; i++)
        acc[i] += __shfl_xor_sync(0xffffffffu, acc[i], 16);
}

__global__ void edge_agg(int sel) {
    const __half* __restrict__ h = sel ? g_h16B : g_h16A;
    int w = (blockIdx.x * blockDim.x + threadIdx.x) >> 5;
    int lane = threadIdx.x & 31;
    if (w >= N_EDGES) return;
    int beg = g_eoff[w], end = g_eoff[w + 1];
    int m = end - beg;
    float acc[8] = {0.f, 0.f, 0.f, 0.f, 0.f, 0.f, 0.f, 0.f};
    seg_sum(g_enodes, beg, m, h, lane, acc);
    if (lane < 16) {
        float inv = 1.0f / fmaxf((float)m, 1.0f);
        __half2 p0 = __floats2half2_rn(acc[0] * inv, acc[1] * inv);
        __half2 p1 = __floats2half2_rn(acc[2] * inv, acc[3] * inv);
        __half2 p2 = __floats2half2_rn(acc[4] * inv, acc[5] * inv);
        __half2 p3 = __floats2half2_rn(acc[6] * inv, acc[7] * inv);
        uint4 u;
        u.x = *reinterpret_cast<unsigned*>(&p0);
        u.y = *reinterpret_cast<unsigned*>(&p1);
        u.z = *reinterpret_cast<unsigned*>(&p2);
        u.w = *reinterpret_cast<unsigned*>(&p3);
        ((uint4*)(g_ef16 + (size_t)w * HID))[lane] = u;
    }
}

// to_out: 0 = write g_h16B (fp16) + accumulate column sums into g_gsum2;
//         1 = write d_out (fp32)
__global__ void node_agg(float* __restrict__ out_arg, int to_out) {
    __shared__ float sCol[HID];
    int w = (blockIdx.x * blockDim.x + threadIdx.x) >> 5;
    int lane = threadIdx.x & 31;
    int tid = threadIdx.x;
    if (!to_out) {
        if (tid < HID) sCol[tid] = 0.f;
        __syncthreads();
    }
    int beg = g_noff[w], end = g_noff[w + 1];
    int m = end - beg;
    float acc[8] = {0.f, 0.f, 0.f, 0.f, 0.f, 0.f, 0.f, 0.f};
    seg_sum(g_nedges, beg, m, g_ef16, lane, acc);
    float inv = 1.0f / fmaxf((float)m, 1.0f);
    float r[8];
    if (lane < 16) {
        float4 s0 = ((const float4*)g_scale)[lane * 2];
        float4 s1 = ((const float4*)g_scale)[lane * 2 + 1];
        r[0] = fmaxf(acc[0] * inv * s0.x, 0.f);
        r[1] = fmaxf(acc[1] * inv * s0.y, 0.f);
        r[2] = fmaxf(acc[2] * inv * s0.z, 0.f);
        r[3] = fmaxf(acc[3] * inv * s0.w, 0.f);
        r[4] = fmaxf(acc[4] * inv * s1.x, 0.f);
        r[5] = fmaxf(acc[5] * inv * s1.y, 0.f);
        r[6] = fmaxf(acc[6] * inv * s1.z, 0.f);
        r[7] = fmaxf(acc[7] * inv * s1.w, 0.f);
        if (to_out) {
            float* orow = out_arg + (size_t)w * HID + lane * 8;
            *(float4*)orow = make_float4(r[0], r[1], r[2], r[3]);
            *(float4*)(orow + 4) = make_float4(r[4], r[5], r[6], r[7]);
        } else {
            __half2 p0 = __floats2half2_rn(r[0], r[1]);
            __half2 p1 = __floats2half2_rn(r[2], r[3]);
            __half2 p2 = __floats2half2_rn(r[4], r[5]);
            __half2 p3 = __floats2half2_rn(r[6], r[7]);
            uint4 u;
            u.x = *reinterpret_cast<unsigned*>(&p0);
            u.y = *reinterpret_cast<unsigned*>(&p1);
            u.z = *reinterpret_cast<unsigned*>(&p2);
            u.w = *reinterpret_cast<unsigned*>(&p3);
            ((uint4*)(g_h16B + (size_t)w * HID))[lane] = u;
#pragma unroll
            for (int i = 0; i < 8; i++)
                atomicAdd(&sCol[lane * 8 + i], r[i]);
        }
    }
    if (!to_out) {
        __syncthreads();
        if (tid < HID) atomicAdd(&g_gsum2[tid], sCol[tid]);
    }
}

// ---------------- launch (R11/R14 schedule, verbatim) ----------------
extern "C" void kernel_launch(void* const* d_in, const int* in_sizes, int n_in,
                              void* d_out, int out_size) {
    const float* text = (const float*)d_in[0];
    const float* Wp   = (const float*)d_in[1];
    const float* bp   = (const float*)d_in[2];
    const float* W1a  = (const float*)d_in[3];
    const float* b1a  = (const float*)d_in[4];
    const float* W2a  = (const float*)d_in[5];
    const float* b2a  = (const float*)d_in[6];
    const float* W1b  = (const float*)d_in[7];
    const float* b1b  = (const float*)d_in[8];
    const float* W2b  = (const float*)d_in[9];
    const float* b2b  = (const float*)d_in[10];
    const int* node_idx = (const int*)d_in[11];
    const int* edge_idx = (const int*)d_in[12];

    const int SMEM_GEMM = 2 * 128 * SSTR * 2;  // 36864 B

    static cudaStream_t s2 = nullptr;
    static cudaEvent_t ev0, evCSR, evG, evS1, evN0, evS2;
    if (!s2) {
        cudaStreamCreateWithFlags(&s2, cudaStreamNonBlocking);
        cudaEventCreateWithFlags(&ev0,   cudaEventDisableTiming);
        cudaEventCreateWithFlags(&evCSR, cudaEventDisableTiming);
        cudaEventCreateWithFlags(&evG,   cudaEventDisableTiming);
        cudaEventCreateWithFlags(&evS1,  cudaEventDisableTiming);
        cudaEventCreateWithFlags(&evN0,  cudaEventDisableTiming);
        cudaEventCreateWithFlags(&evS2,  cudaEventDisableTiming);
        cudaFuncSetAttribute(gemm_mma,
            cudaFuncAttributeMaxDynamicSharedMemorySize, SMEM_GEMM);
    }

    cudaEventRecord(ev0, 0);
    cudaStreamWaitEvent(s2, ev0, 0);

    // launches: #1,#2 on s2; #3 w_prep; #4 gemm_mma (ncu profiles the 4th)
    zero_counts<<<NBN, 256, 0, s2>>>();
    hist_kernel<<<NBI, 256, 0, s2>>>(node_idx, edge_idx);
    w_prep<<<(TD * HID + 255) / 256, 256>>>(Wp);
    gemm_mma<<<(N_NODES + 127) / 128, 256, SMEM_GEMM>>>(text, bp);
    cudaEventRecord(evG, 0);

    segB<<<NBE + NBN, 256, 0, s2>>>();
    scanB<<<2, 512, 0, s2>>>();
    scanfB<<<NBE + NBN, 256, 0, s2>>>();
    csr_fill<<<NBI, 256, 0, s2>>>(node_idx, edge_idx);
    cudaEventRecord(evCSR, s2);

    // layer-1 hypernet on s2 (needs g_gsum from gemm), overlaps edge_agg
    cudaStreamWaitEvent(s2, evG, 0);
    mk_scale<<<1, 128, 0, s2>>>(0, W1a, b1a, W2a, b2a);
    cudaEventRecord(evS1, s2);

    cudaStreamWaitEvent((cudaStream_t)0, evCSR, 0);
    edge_agg<<<N_EDGES / 8, 256>>>(0);
    cudaStreamWaitEvent((cudaStream_t)0, evS1, 0);
    node_agg<<<N_NODES / 8, 256>>>((float*)d_out, 0);
    cudaEventRecord(evN0, 0);

    // layer-2 hypernet on s2 (needs g_gsum2 from node_agg), overlaps edge_agg
    cudaStreamWaitEvent(s2, evN0, 0);
    mk_scale<<<1, 128, 0, s2>>>(1, W1b, b1b, W2b, b2b);
    cudaEventRecord(evS2, s2);

    edge_agg<<<N_EDGES / 8, 256>>>(1);
    cudaStreamWaitEvent((cudaStream_t)0, evS2, 0);
    node_agg<<<N_NODES / 8, 256>>>((float*)d_out, 1);
}